// round 11
// baseline (speedup 1.0000x reference)
#include <cuda_runtime.h>
#include <math.h>

// Problem constants
#define Bb   32
#define Ss   1024
#define Hh   256
#define Pp   96
#define Ll   200
#define Oo   200
#define Ee   64
#define Mtot (Bb*Ss)   // 32768

// Scratch
__device__ float g_h  [3u*Mtot*Ll];
__device__ float g_hid[3u*Mtot*Ll];
__device__ float g_qkv[3u*Mtot*Hh];
__device__ float g_ctx[(unsigned)Mtot*Hh];
__device__ float g_eco[Bb*Hh];

// ---------------------------------------------------------------------------
__global__ void eco_kernel(const float* __restrict__ eco_data,
                           const float* __restrict__ W_eco,
                           const float* __restrict__ b_eco,
                           float* __restrict__ out)
{
    int b = blockIdx.x;
    int h = threadIdx.x;
    float acc = b_eco[h];
    #pragma unroll 8
    for (int e = 0; e < Ee; e++)
        acc = fmaf(eco_data[b*Ee + e], W_eco[e*Hh + h], acc);
    out[b*Hh + h] = acc;
}

// ---------------------------------------------------------------------------
// Scalar fp32 GEMM, 128x128 CTA tile, 8x8 per thread in 2x2 strips of 4
// (conflict-free LDS.128 phases), double-buffered smem.
// MODE 0: h-init   C = tanh(acc + timef[row]*Wt[col] + bias[col])
// MODE 1: hid      C = tanh(acc + bias[col])
// MODE 2: update   C += 0.25*(acc + bias[col])
// MODE 3: qkv      C = mask(row) * (acc + bias[col] + eco[b(row)][col])
// MODE 4: head     C = acc + bias[col]
// ---------------------------------------------------------------------------
template<int MODE>
__global__ __launch_bounds__(256, 2)
void gemm_kernel(const float* __restrict__ A, const float* __restrict__ W,
                 float* __restrict__ C,
                 int M, int N, int K,
                 long aStride, long wStride, long cStride, int biasStride,
                 const float* __restrict__ bias,
                 const float* __restrict__ aux1,
                 const float* __restrict__ aux2, int aux2Stride)
{
    int kb = blockIdx.z;
    A += (long)kb * aStride;
    W += (long)kb * wStride;
    C += (long)kb * cStride;
    const float* bptr = bias + (long)kb * biasStride;
    const float* a2   = aux2 ? (aux2 + (long)kb * aux2Stride) : nullptr;

    __shared__ __align__(16) float As[2][16][132];   // [k][row], transposed A
    __shared__ __align__(16) float Ws[2][16][132];   // [k][col]

    int tid = threadIdx.x;
    int tx = tid & 15, ty = tid >> 4;
    long m0 = (long)blockIdx.x * 128;
    int  n0 = blockIdx.y * 128;

    int aRow0 = tid >> 2,         aK0 = (tid & 3) * 4;
    int aRow1 = (tid + 256) >> 2, aK1 = aK0;
    int wR0 = tid >> 5,           wC0 = (tid & 31) * 4;
    int wR1 = (tid + 256) >> 5,   wC1 = wC0;

    int P = (K + 15) >> 4;

    float4 ar0, ar1, wr0, wr1;
    const float4 z4 = make_float4(0.f, 0.f, 0.f, 0.f);

    {
        int k0 = 0;
        ar0 = (k0 + aK0 + 3 < K) ? *(const float4*)&A[(m0 + aRow0)*K + k0 + aK0] : z4;
        ar1 = (k0 + aK1 + 3 < K) ? *(const float4*)&A[(m0 + aRow1)*K + k0 + aK1] : z4;
        wr0 = (k0 + wR0 < K && n0 + wC0 + 3 < N) ? *(const float4*)&W[(long)(k0 + wR0)*N + n0 + wC0] : z4;
        wr1 = (k0 + wR1 < K && n0 + wC1 + 3 < N) ? *(const float4*)&W[(long)(k0 + wR1)*N + n0 + wC1] : z4;
        As[0][aK0 + 0][aRow0] = ar0.x; As[0][aK0 + 1][aRow0] = ar0.y;
        As[0][aK0 + 2][aRow0] = ar0.z; As[0][aK0 + 3][aRow0] = ar0.w;
        As[0][aK1 + 0][aRow1] = ar1.x; As[0][aK1 + 1][aRow1] = ar1.y;
        As[0][aK1 + 2][aRow1] = ar1.z; As[0][aK1 + 3][aRow1] = ar1.w;
        *(float4*)&Ws[0][wR0][wC0] = wr0;
        *(float4*)&Ws[0][wR1][wC1] = wr1;
    }
    __syncthreads();

    float acc[8][8];
    #pragma unroll
    for (int i = 0; i < 8; i++)
        #pragma unroll
        for (int j = 0; j < 8; j++) acc[i][j] = 0.f;

    for (int p = 0; p < P; p++) {
        int cur = p & 1, nxt = cur ^ 1;
        if (p + 1 < P) {
            int k0 = (p + 1) << 4;
            ar0 = (k0 + aK0 + 3 < K) ? *(const float4*)&A[(m0 + aRow0)*K + k0 + aK0] : z4;
            ar1 = (k0 + aK1 + 3 < K) ? *(const float4*)&A[(m0 + aRow1)*K + k0 + aK1] : z4;
            wr0 = (k0 + wR0 < K && n0 + wC0 + 3 < N) ? *(const float4*)&W[(long)(k0 + wR0)*N + n0 + wC0] : z4;
            wr1 = (k0 + wR1 < K && n0 + wC1 + 3 < N) ? *(const float4*)&W[(long)(k0 + wR1)*N + n0 + wC1] : z4;
        }
        #pragma unroll
        for (int kk = 0; kk < 16; kk++) {
            float4 a0 = *(const float4*)&As[cur][kk][ty*4];
            float4 a1 = *(const float4*)&As[cur][kk][64 + ty*4];
            float4 b0 = *(const float4*)&Ws[cur][kk][tx*4];
            float4 b1 = *(const float4*)&Ws[cur][kk][64 + tx*4];
            float av[8] = {a0.x, a0.y, a0.z, a0.w, a1.x, a1.y, a1.z, a1.w};
            float bv[8] = {b0.x, b0.y, b0.z, b0.w, b1.x, b1.y, b1.z, b1.w};
            #pragma unroll
            for (int i = 0; i < 8; i++)
                #pragma unroll
                for (int j = 0; j < 8; j++)
                    acc[i][j] = fmaf(av[i], bv[j], acc[i][j]);
        }
        if (p + 1 < P) {
            As[nxt][aK0 + 0][aRow0] = ar0.x; As[nxt][aK0 + 1][aRow0] = ar0.y;
            As[nxt][aK0 + 2][aRow0] = ar0.z; As[nxt][aK0 + 3][aRow0] = ar0.w;
            As[nxt][aK1 + 0][aRow1] = ar1.x; As[nxt][aK1 + 1][aRow1] = ar1.y;
            As[nxt][aK1 + 2][aRow1] = ar1.z; As[nxt][aK1 + 3][aRow1] = ar1.w;
            *(float4*)&Ws[nxt][wR0][wC0] = wr0;
            *(float4*)&Ws[nxt][wR1][wC1] = wr1;
        }
        __syncthreads();
    }

    // epilogue over 2x2 strips
    #pragma unroll
    for (int si = 0; si < 2; si++) {
        #pragma unroll
        for (int i = 0; i < 4; i++) {
            long row = m0 + si*64 + ty*4 + i;
            float tf   = (MODE == 0) ? aux1[row] : 0.f;
            float last = (MODE == 3) ? aux1[row*Hh + (Hh-1)] : 0.f;
            #pragma unroll
            for (int sj = 0; sj < 2; sj++) {
                #pragma unroll
                for (int j = 0; j < 4; j++) {
                    int col = n0 + sj*64 + tx*4 + j;
                    if (col >= N) continue;
                    float v = acc[si*4 + i][sj*4 + j];
                    long o = row*N + col;
                    if (MODE == 0) {
                        C[o] = tanhf(v + tf*a2[col] + bptr[col]);
                    } else if (MODE == 1) {
                        C[o] = tanhf(v + bptr[col]);
                    } else if (MODE == 2) {
                        C[o] = C[o] + 0.25f*(v + bptr[col]);
                    } else if (MODE == 3) {
                        v += bptr[col] + a2[(int)(row >> 10)*Hh + col];
                        C[o] = (last == 0.f) ? 0.f : v;
                    } else {
                        C[o] = v + bptr[col];
                    }
                }
            }
        }
    }
}

// ---------------------------------------------------------------------------
// Attention: one CTA per (b, 32-row q-tile).
// Phase 1: 128-key x 128-d K tiles, chunk-swizzled; thread = 4 rows x 4 keys.
// smem: Sc[32*1024] + Qs[32*256] + Ks[128*128] = 229376 B
// ---------------------------------------------------------------------------
__global__ __launch_bounds__(256)
void attn_kernel(const float* __restrict__ qkv, float* __restrict__ ctx)
{
    extern __shared__ float sm[];
    float* Sc = sm;                    // 32*1024
    float* Qs = Sc + 32*1024;          // 32*256
    float* Ks = Qs + 32*256;           // 128 d x 128 keys (chunk-swizzled)

    int b  = blockIdx.y;
    int q0 = blockIdx.x * 32;
    const float* Qg = qkv              + (long)b*Ss*Hh + (long)q0*Hh;
    const float* Kg = qkv + 1L*Mtot*Hh + (long)b*Ss*Hh;
    const float* Vg = qkv + 2L*Mtot*Hh + (long)b*Ss*Hh;

    int tid = threadIdx.x;
    for (int i = tid; i < 32*64; i += 256)
        ((float4*)Qs)[i] = ((const float4*)Qg)[i];

    int tx = tid & 31;          // key chunk (4 keys)
    int ty = tid >> 5;          // row group: rows ty*4 .. ty*4+3
    const float scale = 0.0625f;   // 1/sqrt(256)

    int ld = tid & 127;         // loader: d within half
    int lkh = tid >> 7;         // loader: key half (0/1)

    // ---- Phase 1: scores = Q K^T * scale ----
    for (int kt = 0; kt < 8; kt++) {            // 128-key tiles
        float acc[4][4];
        #pragma unroll
        for (int i = 0; i < 4; i++)
            #pragma unroll
            for (int j = 0; j < 4; j++) acc[i][j] = 0.f;

        #pragma unroll
        for (int h = 0; h < 2; h++) {           // 128-d halves
            __syncthreads();
            // load K[kt*128 + key][h*128 + d] -> Ks[d][key] swizzled
            {
                const float* src = Kg + (long)(kt*128 + lkh*64)*Hh + h*128 + ld;
                #pragma unroll 8
                for (int it = 0; it < 64; it++) {
                    int key = lkh*64 + it;
                    int c = key >> 2, e = key & 3;
                    int cs = c ^ (ld & 31);
                    Ks[ld*128 + cs*4 + e] = src[(long)it*Hh];
                }
            }
            __syncthreads();

            for (int d4 = 0; d4 < 128; d4 += 4) {
                float4 qf[4];
                #pragma unroll
                for (int i = 0; i < 4; i++)
                    qf[i] = *(const float4*)&Qs[(ty*4 + i)*256 + h*128 + d4];
                float qv[4][4] = {
                    {qf[0].x, qf[0].y, qf[0].z, qf[0].w},
                    {qf[1].x, qf[1].y, qf[1].z, qf[1].w},
                    {qf[2].x, qf[2].y, qf[2].z, qf[2].w},
                    {qf[3].x, qf[3].y, qf[3].z, qf[3].w}};
                #pragma unroll
                for (int dd = 0; dd < 4; dd++) {
                    int dr = d4 + dd;
                    int cs = tx ^ (dr & 31);
                    float4 kv = *(const float4*)&Ks[dr*128 + cs*4];
                    float kvv[4] = {kv.x, kv.y, kv.z, kv.w};
                    #pragma unroll
                    for (int i = 0; i < 4; i++)
                        #pragma unroll
                        for (int j = 0; j < 4; j++)
                            acc[i][j] = fmaf(qv[i][dd], kvv[j], acc[i][j]);
                }
            }
        }
        // write scores
        #pragma unroll
        for (int i = 0; i < 4; i++)
            #pragma unroll
            for (int j = 0; j < 4; j++)
                Sc[(ty*4 + i)*1024 + kt*128 + tx*4 + j] = acc[i][j]*scale;
    }
    __syncthreads();

    // ---- Phase 2: softmax, one warp per 4 rows ----
    int lane = tid & 31, w = tid >> 5;
    for (int rr = 0; rr < 4; rr++) {
        int r = w*4 + rr;
        float* row = Sc + r*1024;
        float mx = -1e30f;
        for (int j = lane; j < 1024; j += 32) mx = fmaxf(mx, row[j]);
        #pragma unroll
        for (int o = 16; o; o >>= 1) mx = fmaxf(mx, __shfl_xor_sync(0xffffffffu, mx, o));
        float s = 0.f;
        for (int j = lane; j < 1024; j += 32) {
            float e = __expf(row[j] - mx);
            row[j] = e;
            s += e;
        }
        #pragma unroll
        for (int o = 16; o; o >>= 1) s += __shfl_xor_sync(0xffffffffu, s, o);
        float inv = 1.f / s;
        for (int j = lane; j < 1024; j += 32) row[j] *= inv;
    }
    __syncthreads();

    // ---- Phase 3: ctx = P @ V; thread owns one H column, 32 q-rows ----
    float acc2[32];
    #pragma unroll
    for (int r = 0; r < 32; r++) acc2[r] = 0.f;
    for (int j = 0; j < 1024; j += 4) {
        float v0 = Vg[(long)(j+0)*Hh + tid];
        float v1 = Vg[(long)(j+1)*Hh + tid];
        float v2 = Vg[(long)(j+2)*Hh + tid];
        float v3 = Vg[(long)(j+3)*Hh + tid];
        #pragma unroll
        for (int r = 0; r < 32; r++) {
            float4 p = *(const float4*)&Sc[r*1024 + j];
            acc2[r] = fmaf(p.x, v0, fmaf(p.y, v1, fmaf(p.z, v2, fmaf(p.w, v3, acc2[r]))));
        }
    }
    #pragma unroll
    for (int r = 0; r < 32; r++)
        ctx[(long)b*Ss*Hh + (long)(q0 + r)*Hh + tid] = acc2[r];
}

// ---------------------------------------------------------------------------
extern "C" void kernel_launch(void* const* d_in, const int* in_sizes, int n_in,
                              void* d_out, int out_size)
{
    const float* eco_data = (const float*)d_in[0];
    const float* tran     = (const float*)d_in[1];
    const float* time_x   = (const float*)d_in[3];
    const float* W_eco = (const float*)d_in[6];
    const float* b_eco = (const float*)d_in[7];
    const float* W_in  = (const float*)d_in[8];
    const float* W_t   = (const float*)d_in[9];
    const float* b_in  = (const float*)d_in[10];
    const float* W_f1  = (const float*)d_in[11];
    const float* b_f1  = (const float*)d_in[12];
    const float* W_f2  = (const float*)d_in[13];
    const float* b_f2  = (const float*)d_in[14];
    const float* W_out = (const float*)d_in[15];
    const float* b_out = (const float*)d_in[16];
    const float* W_lin = (const float*)d_in[17];
    const float* b_lin = (const float*)d_in[18];
    float* out = (float*)d_out;

    float *h, *hid, *qkv, *ctx, *eco;
    cudaGetSymbolAddress((void**)&h,   g_h);
    cudaGetSymbolAddress((void**)&hid, g_hid);
    cudaGetSymbolAddress((void**)&qkv, g_qkv);
    cudaGetSymbolAddress((void**)&ctx, g_ctx);
    cudaGetSymbolAddress((void**)&eco, g_eco);

    dim3 blk(256);

    eco_kernel<<<Bb, Hh>>>(eco_data, W_eco, b_eco, eco);

    // h = tanh(tran @ W_in + time_x * W_t + b_in)   [3][M][L]
    gemm_kernel<0><<<dim3(Mtot/128, 2, 3), blk>>>(
        tran, W_in, h, Mtot, Ll, Hh,
        0L, (long)Hh*Ll, (long)Mtot*Ll, Ll, b_in, time_x, W_t, Ll);

    // 4 Euler steps
    for (int it = 0; it < 4; it++) {
        gemm_kernel<1><<<dim3(Mtot/128, 2, 3), blk>>>(
            h, W_f1, hid, Mtot, Oo, Ll,
            (long)Mtot*Ll, (long)Ll*Oo, (long)Mtot*Oo, Oo, b_f1, nullptr, nullptr, 0);
        gemm_kernel<2><<<dim3(Mtot/128, 2, 3), blk>>>(
            hid, W_f2, h, Mtot, Ll, Oo,
            (long)Mtot*Oo, (long)Oo*Ll, (long)Mtot*Ll, Ll, b_f2, nullptr, nullptr, 0);
    }

    // qkv = mask * (h @ W_out + b_out + eco)    [3][M][H]
    gemm_kernel<3><<<dim3(Mtot/128, 2, 3), blk>>>(
        h, W_out, qkv, Mtot, Hh, Ll,
        (long)Mtot*Ll, (long)Ll*Hh, (long)Mtot*Hh, Hh, b_out, tran, eco, 0);

    // attention
    size_t smem = (size_t)(32*1024 + 32*256 + 128*128) * sizeof(float); // 229376
    cudaFuncSetAttribute(attn_kernel, cudaFuncAttributeMaxDynamicSharedMemorySize, (int)smem);
    attn_kernel<<<dim3(Ss/32, Bb), blk, smem>>>(qkv, ctx);

    // out = ctx @ W_lin + b_lin   [M][P]
    gemm_kernel<4><<<dim3(Mtot/128, 1, 1), blk>>>(
        ctx, W_lin, out, Mtot, Pp, Hh,
        0L, 0L, 0L, 0, b_lin, nullptr, nullptr, 0);
}

// round 12
// speedup vs baseline: 1.2258x; 1.2258x over previous
#include <cuda_runtime.h>
#include <math.h>

// Problem constants
#define Bb   32
#define Ss   1024
#define Hh   256
#define Pp   96
#define Ll   200
#define Oo   200
#define Ee   64
#define Mtot (Bb*Ss)   // 32768

// Scratch
__device__ float g_h  [3u*Mtot*Ll];
__device__ float g_hid[3u*Mtot*Ll];
__device__ float g_qkv[3u*Mtot*Hh];
__device__ float g_ctx[(unsigned)Mtot*Hh];
__device__ float g_eco[Bb*Hh];

// ---------------------------------------------------------------------------
__global__ void eco_kernel(const float* __restrict__ eco_data,
                           const float* __restrict__ W_eco,
                           const float* __restrict__ b_eco,
                           float* __restrict__ out)
{
    int b = blockIdx.x;
    int h = threadIdx.x;
    float acc = b_eco[h];
    #pragma unroll 8
    for (int e = 0; e < Ee; e++)
        acc = fmaf(eco_data[b*Ee + e], W_eco[e*Hh + h], acc);
    out[b*Hh + h] = acc;
}

// ---------------------------------------------------------------------------
// Scalar fp32 GEMM (R10, best measured): 128x128 CTA tile, 8x8 per thread,
// double-buffered smem.
// MODE 0: h-init   C = tanh(acc + timef[row]*Wt[col] + bias[col])
// MODE 1: hid      C = tanh(acc + bias[col])
// MODE 2: update   C += 0.25*(acc + bias[col])
// MODE 3: qkv      C = mask(row) * (acc + bias[col] + eco[b(row)][col])
// MODE 4: head     C = acc + bias[col]
// ---------------------------------------------------------------------------
template<int MODE>
__global__ __launch_bounds__(256, 2)
void gemm_kernel(const float* __restrict__ A, const float* __restrict__ W,
                 float* __restrict__ C,
                 int M, int N, int K,
                 long aStride, long wStride, long cStride, int biasStride,
                 const float* __restrict__ bias,
                 const float* __restrict__ aux1,
                 const float* __restrict__ aux2, int aux2Stride)
{
    int kb = blockIdx.z;
    A += (long)kb * aStride;
    W += (long)kb * wStride;
    C += (long)kb * cStride;
    const float* bptr = bias + (long)kb * biasStride;
    const float* a2   = aux2 ? (aux2 + (long)kb * aux2Stride) : nullptr;

    __shared__ __align__(16) float As[2][16][132];   // transposed A: [k][row]
    __shared__ __align__(16) float Ws[2][16][132];   // [k][col]

    int tid = threadIdx.x;
    int tx = tid & 15, ty = tid >> 4;
    long m0 = (long)blockIdx.x * 128;
    int  n0 = blockIdx.y * 128;

    int aRow0 = tid >> 2,         aK0 = (tid & 3) * 4;
    int aRow1 = (tid + 256) >> 2, aK1 = aK0;
    int wR0 = tid >> 5,           wC0 = (tid & 31) * 4;
    int wR1 = (tid + 256) >> 5,   wC1 = wC0;

    int P = (K + 15) >> 4;

    float4 ar0, ar1, wr0, wr1;
    const float4 z4 = make_float4(0.f, 0.f, 0.f, 0.f);

    {
        int k0 = 0;
        ar0 = (k0 + aK0 + 3 < K) ? *(const float4*)&A[(m0 + aRow0)*K + k0 + aK0] : z4;
        ar1 = (k0 + aK1 + 3 < K) ? *(const float4*)&A[(m0 + aRow1)*K + k0 + aK1] : z4;
        wr0 = (k0 + wR0 < K && n0 + wC0 + 3 < N) ? *(const float4*)&W[(long)(k0 + wR0)*N + n0 + wC0] : z4;
        wr1 = (k0 + wR1 < K && n0 + wC1 + 3 < N) ? *(const float4*)&W[(long)(k0 + wR1)*N + n0 + wC1] : z4;
        As[0][aK0 + 0][aRow0] = ar0.x; As[0][aK0 + 1][aRow0] = ar0.y;
        As[0][aK0 + 2][aRow0] = ar0.z; As[0][aK0 + 3][aRow0] = ar0.w;
        As[0][aK1 + 0][aRow1] = ar1.x; As[0][aK1 + 1][aRow1] = ar1.y;
        As[0][aK1 + 2][aRow1] = ar1.z; As[0][aK1 + 3][aRow1] = ar1.w;
        *(float4*)&Ws[0][wR0][wC0] = wr0;
        *(float4*)&Ws[0][wR1][wC1] = wr1;
    }
    __syncthreads();

    float acc[8][8];
    #pragma unroll
    for (int i = 0; i < 8; i++)
        #pragma unroll
        for (int j = 0; j < 8; j++) acc[i][j] = 0.f;

    for (int p = 0; p < P; p++) {
        int cur = p & 1, nxt = cur ^ 1;
        if (p + 1 < P) {
            int k0 = (p + 1) << 4;
            ar0 = (k0 + aK0 + 3 < K) ? *(const float4*)&A[(m0 + aRow0)*K + k0 + aK0] : z4;
            ar1 = (k0 + aK1 + 3 < K) ? *(const float4*)&A[(m0 + aRow1)*K + k0 + aK1] : z4;
            wr0 = (k0 + wR0 < K && n0 + wC0 + 3 < N) ? *(const float4*)&W[(long)(k0 + wR0)*N + n0 + wC0] : z4;
            wr1 = (k0 + wR1 < K && n0 + wC1 + 3 < N) ? *(const float4*)&W[(long)(k0 + wR1)*N + n0 + wC1] : z4;
        }
        #pragma unroll
        for (int kk = 0; kk < 16; kk++) {
            float4 a0 = *(const float4*)&As[cur][kk][ty*8];
            float4 a1 = *(const float4*)&As[cur][kk][ty*8 + 4];
            float4 b0 = *(const float4*)&Ws[cur][kk][tx*8];
            float4 b1 = *(const float4*)&Ws[cur][kk][tx*8 + 4];
            float av[8] = {a0.x, a0.y, a0.z, a0.w, a1.x, a1.y, a1.z, a1.w};
            float bv[8] = {b0.x, b0.y, b0.z, b0.w, b1.x, b1.y, b1.z, b1.w};
            #pragma unroll
            for (int i = 0; i < 8; i++)
                #pragma unroll
                for (int j = 0; j < 8; j++)
                    acc[i][j] = fmaf(av[i], bv[j], acc[i][j]);
        }
        if (p + 1 < P) {
            As[nxt][aK0 + 0][aRow0] = ar0.x; As[nxt][aK0 + 1][aRow0] = ar0.y;
            As[nxt][aK0 + 2][aRow0] = ar0.z; As[nxt][aK0 + 3][aRow0] = ar0.w;
            As[nxt][aK1 + 0][aRow1] = ar1.x; As[nxt][aK1 + 1][aRow1] = ar1.y;
            As[nxt][aK1 + 2][aRow1] = ar1.z; As[nxt][aK1 + 3][aRow1] = ar1.w;
            *(float4*)&Ws[nxt][wR0][wC0] = wr0;
            *(float4*)&Ws[nxt][wR1][wC1] = wr1;
        }
        __syncthreads();
    }

    #pragma unroll
    for (int i = 0; i < 8; i++) {
        long row = m0 + ty*8 + i;
        float tf   = (MODE == 0) ? aux1[row] : 0.f;
        float last = (MODE == 3) ? aux1[row*Hh + (Hh-1)] : 0.f;
        #pragma unroll
        for (int j = 0; j < 8; j++) {
            int col = n0 + tx*8 + j;
            if (col >= N) continue;
            float v = acc[i][j];
            long o = row*N + col;
            if (MODE == 0) {
                C[o] = tanhf(v + tf*a2[col] + bptr[col]);
            } else if (MODE == 1) {
                C[o] = tanhf(v + bptr[col]);
            } else if (MODE == 2) {
                C[o] = C[o] + 0.25f*(v + bptr[col]);
            } else if (MODE == 3) {
                v += bptr[col] + a2[(int)(row >> 10)*Hh + col];
                C[o] = (last == 0.f) ? 0.f : v;
            } else {
                C[o] = v + bptr[col];
            }
        }
    }
}

// ---------------------------------------------------------------------------
// Attention, 512 threads (16 warps) per CTA, one CTA per (b, 32-row q-tile).
// Same smem layout as R3: Sc[32][1024] + Qs[32][256] + Ks[256][65] = 230400 B
// ---------------------------------------------------------------------------
__global__ __launch_bounds__(512)
void attn_kernel(const float* __restrict__ qkv, float* __restrict__ ctx)
{
    extern __shared__ float sm[];
    float* Sc = sm;                    // 32*1024
    float* Qs = Sc + 32*1024;          // 32*256 (phase 3: reused as ctx staging)
    float* Ks = Qs + 32*256;           // 256*65

    int b  = blockIdx.y;
    int q0 = blockIdx.x * 32;
    const float* Qg = qkv              + (long)b*Ss*Hh + (long)q0*Hh;
    const float* Kg = qkv + 1L*Mtot*Hh + (long)b*Ss*Hh;
    const float* Vg = qkv + 2L*Mtot*Hh + (long)b*Ss*Hh;

    int tid = threadIdx.x;
    for (int i = tid; i < 32*256; i += 512) Qs[i] = Qg[i];
    __syncthreads();

    const float scale = 0.0625f;   // 1/sqrt(256)

    // ---- Phase 1: scores = Q K^T * scale, key tiles of 64 ----
    int row = tid >> 4;            // 0..31
    int tx  = tid & 15;            // key group of 4
    int lD  = tid & 255;           // loader d
    int lH  = (tid >> 8) * 32;     // loader key-half base (0 or 32)

    for (int kt = 0; kt < 16; kt++) {
        // load K tile transposed: Ks[d*65 + key]; warps read 128B coalesced
        {
            const float* src = Kg + (long)(kt*64 + lH)*Hh + lD;
            #pragma unroll 8
            for (int it = 0; it < 32; it++)
                Ks[lD*65 + lH + it] = src[(long)it*Hh];
        }
        __syncthreads();

        float acc[4] = {};
        for (int d = 0; d < 256; d += 4) {
            float4 q = *(const float4*)&Qs[row*256 + d];
            float qv[4] = {q.x, q.y, q.z, q.w};
            #pragma unroll
            for (int dd = 0; dd < 4; dd++) {
                #pragma unroll
                for (int j = 0; j < 4; j++) {
                    float kv = Ks[(d + dd)*65 + tx*4 + j];
                    acc[j] = fmaf(qv[dd], kv, acc[j]);
                }
            }
        }
        #pragma unroll
        for (int j = 0; j < 4; j++)
            Sc[row*1024 + kt*64 + tx*4 + j] = acc[j]*scale;
        __syncthreads();
    }

    // ---- Phase 2: softmax, one warp per 2 rows ----
    int lane = tid & 31, w = tid >> 5;
    for (int rr = 0; rr < 2; rr++) {
        int r = w*2 + rr;
        float* rowp = Sc + r*1024;
        float mx = -1e30f;
        for (int j = lane; j < 1024; j += 32) mx = fmaxf(mx, rowp[j]);
        #pragma unroll
        for (int o = 16; o; o >>= 1) mx = fmaxf(mx, __shfl_xor_sync(0xffffffffu, mx, o));
        float s = 0.f;
        for (int j = lane; j < 1024; j += 32) {
            float e = __expf(rowp[j] - mx);
            rowp[j] = e;
            s += e;
        }
        #pragma unroll
        for (int o = 16; o; o >>= 1) s += __shfl_xor_sync(0xffffffffu, s, o);
        float inv = 1.f / s;
        for (int j = lane; j < 1024; j += 32) rowp[j] *= inv;
    }
    __syncthreads();

    // ---- Phase 3: ctx = P @ V, key-split across thread halves ----
    int c  = tid & 255;            // H column
    int kh = tid >> 8;             // key half (0/1)
    const float* Vh = Vg + (long)kh*512*Hh;
    const float* Ph = Sc + kh*512;

    float acc2[32];
    #pragma unroll
    for (int r = 0; r < 32; r++) acc2[r] = 0.f;
    for (int j = 0; j < 512; j += 4) {
        float v0 = Vh[(long)(j+0)*Hh + c];
        float v1 = Vh[(long)(j+1)*Hh + c];
        float v2 = Vh[(long)(j+2)*Hh + c];
        float v3 = Vh[(long)(j+3)*Hh + c];
        #pragma unroll
        for (int r = 0; r < 32; r++) {
            float4 p = *(const float4*)&Ph[r*1024 + j];
            acc2[r] = fmaf(p.x, v0, fmaf(p.y, v1, fmaf(p.z, v2, fmaf(p.w, v3, acc2[r]))));
        }
    }
    // combine halves via Qs staging (Qs no longer needed)
    if (kh == 0) {
        #pragma unroll
        for (int r = 0; r < 32; r++) Qs[r*256 + c] = acc2[r];
    }
    __syncthreads();
    if (kh == 1) {
        #pragma unroll
        for (int r = 0; r < 32; r++)
            ctx[(long)b*Ss*Hh + (long)(q0 + r)*Hh + c] = Qs[r*256 + c] + acc2[r];
    }
}

// ---------------------------------------------------------------------------
extern "C" void kernel_launch(void* const* d_in, const int* in_sizes, int n_in,
                              void* d_out, int out_size)
{
    const float* eco_data = (const float*)d_in[0];
    const float* tran     = (const float*)d_in[1];
    const float* time_x   = (const float*)d_in[3];
    const float* W_eco = (const float*)d_in[6];
    const float* b_eco = (const float*)d_in[7];
    const float* W_in  = (const float*)d_in[8];
    const float* W_t   = (const float*)d_in[9];
    const float* b_in  = (const float*)d_in[10];
    const float* W_f1  = (const float*)d_in[11];
    const float* b_f1  = (const float*)d_in[12];
    const float* W_f2  = (const float*)d_in[13];
    const float* b_f2  = (const float*)d_in[14];
    const float* W_out = (const float*)d_in[15];
    const float* b_out = (const float*)d_in[16];
    const float* W_lin = (const float*)d_in[17];
    const float* b_lin = (const float*)d_in[18];
    float* out = (float*)d_out;

    float *h, *hid, *qkv, *ctx, *eco;
    cudaGetSymbolAddress((void**)&h,   g_h);
    cudaGetSymbolAddress((void**)&hid, g_hid);
    cudaGetSymbolAddress((void**)&qkv, g_qkv);
    cudaGetSymbolAddress((void**)&ctx, g_ctx);
    cudaGetSymbolAddress((void**)&eco, g_eco);

    dim3 blk(256);

    eco_kernel<<<Bb, Hh>>>(eco_data, W_eco, b_eco, eco);

    // h = tanh(tran @ W_in + time_x * W_t + b_in)   [3][M][L]
    gemm_kernel<0><<<dim3(Mtot/128, 2, 3), blk>>>(
        tran, W_in, h, Mtot, Ll, Hh,
        0L, (long)Hh*Ll, (long)Mtot*Ll, Ll, b_in, time_x, W_t, Ll);

    // 4 Euler steps
    for (int it = 0; it < 4; it++) {
        gemm_kernel<1><<<dim3(Mtot/128, 2, 3), blk>>>(
            h, W_f1, hid, Mtot, Oo, Ll,
            (long)Mtot*Ll, (long)Ll*Oo, (long)Mtot*Oo, Oo, b_f1, nullptr, nullptr, 0);
        gemm_kernel<2><<<dim3(Mtot/128, 2, 3), blk>>>(
            hid, W_f2, h, Mtot, Ll, Oo,
            (long)Mtot*Oo, (long)Oo*Ll, (long)Mtot*Ll, Ll, b_f2, nullptr, nullptr, 0);
    }

    // qkv = mask * (h @ W_out + b_out + eco)    [3][M][H]
    gemm_kernel<3><<<dim3(Mtot/128, 2, 3), blk>>>(
        h, W_out, qkv, Mtot, Hh, Ll,
        (long)Mtot*Ll, (long)Ll*Hh, (long)Mtot*Hh, Hh, b_out, tran, eco, 0);

    // attention (512 threads)
    size_t smem = (size_t)(32*1024 + 32*256 + 256*65) * sizeof(float); // 230400
    cudaFuncSetAttribute(attn_kernel, cudaFuncAttributeMaxDynamicSharedMemorySize, (int)smem);
    attn_kernel<<<dim3(Ss/32, Bb), 512, smem>>>(qkv, ctx);

    // out = ctx @ W_lin + b_lin   [M][P]
    gemm_kernel<4><<<dim3(Mtot/128, 1, 1), blk>>>(
        ctx, W_lin, out, Mtot, Pp, Hh,
        0L, 0L, 0L, 0, b_lin, nullptr, nullptr, 0);
}

// round 13
// speedup vs baseline: 1.3198x; 1.0767x over previous
#include <cuda_runtime.h>
#include <math.h>

// Problem constants
#define Bb   32
#define Ss   1024
#define Hh   256
#define Pp   96
#define Ll   200
#define Oo   200
#define Ee   64
#define Mtot (Bb*Ss)   // 32768

// Scratch
__device__ float g_h  [3u*Mtot*Ll];
__device__ float g_hid[3u*Mtot*Ll];
__device__ float g_qkv[3u*Mtot*Hh];
__device__ float g_ctx[(unsigned)Mtot*Hh];
__device__ float g_eco[Bb*Hh];

// ---------------------------------------------------------------------------
__global__ void eco_kernel(const float* __restrict__ eco_data,
                           const float* __restrict__ W_eco,
                           const float* __restrict__ b_eco,
                           float* __restrict__ out)
{
    int b = blockIdx.x;
    int h = threadIdx.x;
    float acc = b_eco[h];
    #pragma unroll 8
    for (int e = 0; e < Ee; e++)
        acc = fmaf(eco_data[b*Ee + e], W_eco[e*Hh + h], acc);
    out[b*Hh + h] = acc;
}

// ---------------------------------------------------------------------------
// Scalar fp32 GEMM (R10, best measured): 128x128 CTA tile, 8x8 per thread,
// double-buffered smem.
// MODE 0: h-init   C = tanh(acc + timef[row]*Wt[col] + bias[col])
// MODE 1: hid      C = tanh(acc + bias[col])
// MODE 2: update   C += 0.25*(acc + bias[col])
// MODE 3: qkv      C = mask(row) * (acc + bias[col] + eco[b(row)][col])
// MODE 4: head     C = acc + bias[col]
// ---------------------------------------------------------------------------
template<int MODE>
__global__ __launch_bounds__(256, 2)
void gemm_kernel(const float* __restrict__ A, const float* __restrict__ W,
                 float* __restrict__ C,
                 int M, int N, int K,
                 long aStride, long wStride, long cStride, int biasStride,
                 const float* __restrict__ bias,
                 const float* __restrict__ aux1,
                 const float* __restrict__ aux2, int aux2Stride)
{
    int kb = blockIdx.z;
    A += (long)kb * aStride;
    W += (long)kb * wStride;
    C += (long)kb * cStride;
    const float* bptr = bias + (long)kb * biasStride;
    const float* a2   = aux2 ? (aux2 + (long)kb * aux2Stride) : nullptr;

    __shared__ __align__(16) float As[2][16][132];   // transposed A: [k][row]
    __shared__ __align__(16) float Ws[2][16][132];   // [k][col]

    int tid = threadIdx.x;
    int tx = tid & 15, ty = tid >> 4;
    long m0 = (long)blockIdx.x * 128;
    int  n0 = blockIdx.y * 128;

    int aRow0 = tid >> 2,         aK0 = (tid & 3) * 4;
    int aRow1 = (tid + 256) >> 2, aK1 = aK0;
    int wR0 = tid >> 5,           wC0 = (tid & 31) * 4;
    int wR1 = (tid + 256) >> 5,   wC1 = wC0;

    int P = (K + 15) >> 4;

    float4 ar0, ar1, wr0, wr1;
    const float4 z4 = make_float4(0.f, 0.f, 0.f, 0.f);

    {
        int k0 = 0;
        ar0 = (k0 + aK0 + 3 < K) ? *(const float4*)&A[(m0 + aRow0)*K + k0 + aK0] : z4;
        ar1 = (k0 + aK1 + 3 < K) ? *(const float4*)&A[(m0 + aRow1)*K + k0 + aK1] : z4;
        wr0 = (k0 + wR0 < K && n0 + wC0 + 3 < N) ? *(const float4*)&W[(long)(k0 + wR0)*N + n0 + wC0] : z4;
        wr1 = (k0 + wR1 < K && n0 + wC1 + 3 < N) ? *(const float4*)&W[(long)(k0 + wR1)*N + n0 + wC1] : z4;
        As[0][aK0 + 0][aRow0] = ar0.x; As[0][aK0 + 1][aRow0] = ar0.y;
        As[0][aK0 + 2][aRow0] = ar0.z; As[0][aK0 + 3][aRow0] = ar0.w;
        As[0][aK1 + 0][aRow1] = ar1.x; As[0][aK1 + 1][aRow1] = ar1.y;
        As[0][aK1 + 2][aRow1] = ar1.z; As[0][aK1 + 3][aRow1] = ar1.w;
        *(float4*)&Ws[0][wR0][wC0] = wr0;
        *(float4*)&Ws[0][wR1][wC1] = wr1;
    }
    __syncthreads();

    float acc[8][8];
    #pragma unroll
    for (int i = 0; i < 8; i++)
        #pragma unroll
        for (int j = 0; j < 8; j++) acc[i][j] = 0.f;

    for (int p = 0; p < P; p++) {
        int cur = p & 1, nxt = cur ^ 1;
        if (p + 1 < P) {
            int k0 = (p + 1) << 4;
            ar0 = (k0 + aK0 + 3 < K) ? *(const float4*)&A[(m0 + aRow0)*K + k0 + aK0] : z4;
            ar1 = (k0 + aK1 + 3 < K) ? *(const float4*)&A[(m0 + aRow1)*K + k0 + aK1] : z4;
            wr0 = (k0 + wR0 < K && n0 + wC0 + 3 < N) ? *(const float4*)&W[(long)(k0 + wR0)*N + n0 + wC0] : z4;
            wr1 = (k0 + wR1 < K && n0 + wC1 + 3 < N) ? *(const float4*)&W[(long)(k0 + wR1)*N + n0 + wC1] : z4;
        }
        #pragma unroll
        for (int kk = 0; kk < 16; kk++) {
            float4 a0 = *(const float4*)&As[cur][kk][ty*8];
            float4 a1 = *(const float4*)&As[cur][kk][ty*8 + 4];
            float4 b0 = *(const float4*)&Ws[cur][kk][tx*8];
            float4 b1 = *(const float4*)&Ws[cur][kk][tx*8 + 4];
            float av[8] = {a0.x, a0.y, a0.z, a0.w, a1.x, a1.y, a1.z, a1.w};
            float bv[8] = {b0.x, b0.y, b0.z, b0.w, b1.x, b1.y, b1.z, b1.w};
            #pragma unroll
            for (int i = 0; i < 8; i++)
                #pragma unroll
                for (int j = 0; j < 8; j++)
                    acc[i][j] = fmaf(av[i], bv[j], acc[i][j]);
        }
        if (p + 1 < P) {
            As[nxt][aK0 + 0][aRow0] = ar0.x; As[nxt][aK0 + 1][aRow0] = ar0.y;
            As[nxt][aK0 + 2][aRow0] = ar0.z; As[nxt][aK0 + 3][aRow0] = ar0.w;
            As[nxt][aK1 + 0][aRow1] = ar1.x; As[nxt][aK1 + 1][aRow1] = ar1.y;
            As[nxt][aK1 + 2][aRow1] = ar1.z; As[nxt][aK1 + 3][aRow1] = ar1.w;
            *(float4*)&Ws[nxt][wR0][wC0] = wr0;
            *(float4*)&Ws[nxt][wR1][wC1] = wr1;
        }
        __syncthreads();
    }

    #pragma unroll
    for (int i = 0; i < 8; i++) {
        long row = m0 + ty*8 + i;
        float tf   = (MODE == 0) ? aux1[row] : 0.f;
        float last = (MODE == 3) ? aux1[row*Hh + (Hh-1)] : 0.f;
        #pragma unroll
        for (int j = 0; j < 8; j++) {
            int col = n0 + tx*8 + j;
            if (col >= N) continue;
            float v = acc[i][j];
            long o = row*N + col;
            if (MODE == 0) {
                C[o] = tanhf(v + tf*a2[col] + bptr[col]);
            } else if (MODE == 1) {
                C[o] = tanhf(v + bptr[col]);
            } else if (MODE == 2) {
                C[o] = C[o] + 0.25f*(v + bptr[col]);
            } else if (MODE == 3) {
                v += bptr[col] + a2[(int)(row >> 10)*Hh + col];
                C[o] = (last == 0.f) ? 0.f : v;
            } else {
                C[o] = v + bptr[col];
            }
        }
    }
}

// ---------------------------------------------------------------------------
// Attention, 512 threads per CTA, one CTA per (b, 32-row q-tile).
// Phase 1 K tile: 64-wide swizzled rows (16B-aligned -> LDS.128 kv reads).
// smem: Sc[32*1024] + Qs[32*256] + Ks[256*64] = 229376 B
// ---------------------------------------------------------------------------
__global__ __launch_bounds__(512)
void attn_kernel(const float* __restrict__ qkv, float* __restrict__ ctx)
{
    extern __shared__ float sm[];
    float* Sc = sm;                    // 32*1024
    float* Qs = Sc + 32*1024;          // 32*256 (phase 3: reused as ctx staging)
    float* Ks = Qs + 32*256;           // 256 d x 64 keys, key ^ 4*(d&15)

    int b  = blockIdx.y;
    int q0 = blockIdx.x * 32;
    const float* Qg = qkv              + (long)b*Ss*Hh + (long)q0*Hh;
    const float* Kg = qkv + 1L*Mtot*Hh + (long)b*Ss*Hh;
    const float* Vg = qkv + 2L*Mtot*Hh + (long)b*Ss*Hh;

    int tid = threadIdx.x;
    for (int i = tid; i < 32*256; i += 512) Qs[i] = Qg[i];
    __syncthreads();

    const float scale = 0.0625f;   // 1/sqrt(256)

    // ---- Phase 1: scores = Q K^T * scale, key tiles of 64 ----
    int row = tid >> 4;            // 0..31
    int tx  = tid & 15;            // key group of 4
    int lD  = tid & 255;           // loader d
    int lH  = (tid >> 8) * 32;     // loader key-half base (0 or 32)
    int lsw = 4*(lD & 15);         // loader swizzle for this d

    for (int kt = 0; kt < 16; kt++) {
        // load K tile transposed+swizzled: Ks[d*64 + (key ^ 4*(d&15))]
        {
            const float* src = Kg + (long)(kt*64 + lH)*Hh + lD;
            #pragma unroll 8
            for (int it = 0; it < 32; it++)
                Ks[lD*64 + ((lH + it) ^ lsw)] = src[(long)it*Hh];
        }
        __syncthreads();

        float acc[4] = {};
        for (int d = 0; d < 256; d += 4) {
            float4 q = *(const float4*)&Qs[row*256 + d];
            float qv[4] = {q.x, q.y, q.z, q.w};
            #pragma unroll
            for (int dd = 0; dd < 4; dd++) {
                int dr = d + dd;
                float4 kv = *(const float4*)&Ks[dr*64 + ((tx*4) ^ (4*(dr & 15)))];
                acc[0] = fmaf(qv[dd], kv.x, acc[0]);
                acc[1] = fmaf(qv[dd], kv.y, acc[1]);
                acc[2] = fmaf(qv[dd], kv.z, acc[2]);
                acc[3] = fmaf(qv[dd], kv.w, acc[3]);
            }
        }
        #pragma unroll
        for (int j = 0; j < 4; j++)
            Sc[row*1024 + kt*64 + tx*4 + j] = acc[j]*scale;
        __syncthreads();
    }

    // ---- Phase 2: softmax, one warp per 2 rows ----
    int lane = tid & 31, w = tid >> 5;
    for (int rr = 0; rr < 2; rr++) {
        int r = w*2 + rr;
        float* rowp = Sc + r*1024;
        float mx = -1e30f;
        for (int j = lane; j < 1024; j += 32) mx = fmaxf(mx, rowp[j]);
        #pragma unroll
        for (int o = 16; o; o >>= 1) mx = fmaxf(mx, __shfl_xor_sync(0xffffffffu, mx, o));
        float s = 0.f;
        for (int j = lane; j < 1024; j += 32) {
            float e = __expf(rowp[j] - mx);
            rowp[j] = e;
            s += e;
        }
        #pragma unroll
        for (int o = 16; o; o >>= 1) s += __shfl_xor_sync(0xffffffffu, s, o);
        float inv = 1.f / s;
        for (int j = lane; j < 1024; j += 32) rowp[j] *= inv;
    }
    __syncthreads();

    // ---- Phase 3: ctx = P @ V, key-split across thread halves ----
    int c  = tid & 255;            // H column
    int kh = tid >> 8;             // key half (0/1)
    const float* Vh = Vg + (long)kh*512*Hh;
    const float* Ph = Sc + kh*512;

    float acc2[32];
    #pragma unroll
    for (int r = 0; r < 32; r++) acc2[r] = 0.f;
    for (int j = 0; j < 512; j += 4) {
        float v0 = Vh[(long)(j+0)*Hh + c];
        float v1 = Vh[(long)(j+1)*Hh + c];
        float v2 = Vh[(long)(j+2)*Hh + c];
        float v3 = Vh[(long)(j+3)*Hh + c];
        #pragma unroll
        for (int r = 0; r < 32; r++) {
            float4 p = *(const float4*)&Ph[r*1024 + j];
            acc2[r] = fmaf(p.x, v0, fmaf(p.y, v1, fmaf(p.z, v2, fmaf(p.w, v3, acc2[r]))));
        }
    }
    if (kh == 0) {
        #pragma unroll
        for (int r = 0; r < 32; r++) Qs[r*256 + c] = acc2[r];
    }
    __syncthreads();
    if (kh == 1) {
        #pragma unroll
        for (int r = 0; r < 32; r++)
            ctx[(long)b*Ss*Hh + (long)(q0 + r)*Hh + c] = Qs[r*256 + c] + acc2[r];
    }
}

// ---------------------------------------------------------------------------
extern "C" void kernel_launch(void* const* d_in, const int* in_sizes, int n_in,
                              void* d_out, int out_size)
{
    const float* eco_data = (const float*)d_in[0];
    const float* tran     = (const float*)d_in[1];
    const float* time_x   = (const float*)d_in[3];
    const float* W_eco = (const float*)d_in[6];
    const float* b_eco = (const float*)d_in[7];
    const float* W_in  = (const float*)d_in[8];
    const float* W_t   = (const float*)d_in[9];
    const float* b_in  = (const float*)d_in[10];
    const float* W_f1  = (const float*)d_in[11];
    const float* b_f1  = (const float*)d_in[12];
    const float* W_f2  = (const float*)d_in[13];
    const float* b_f2  = (const float*)d_in[14];
    const float* W_out = (const float*)d_in[15];
    const float* b_out = (const float*)d_in[16];
    const float* W_lin = (const float*)d_in[17];
    const float* b_lin = (const float*)d_in[18];
    float* out = (float*)d_out;

    float *h, *hid, *qkv, *ctx, *eco;
    cudaGetSymbolAddress((void**)&h,   g_h);
    cudaGetSymbolAddress((void**)&hid, g_hid);
    cudaGetSymbolAddress((void**)&qkv, g_qkv);
    cudaGetSymbolAddress((void**)&ctx, g_ctx);
    cudaGetSymbolAddress((void**)&eco, g_eco);

    dim3 blk(256);

    eco_kernel<<<Bb, Hh>>>(eco_data, W_eco, b_eco, eco);

    // h = tanh(tran @ W_in + time_x * W_t + b_in)   [3][M][L]
    gemm_kernel<0><<<dim3(Mtot/128, 2, 3), blk>>>(
        tran, W_in, h, Mtot, Ll, Hh,
        0L, (long)Hh*Ll, (long)Mtot*Ll, Ll, b_in, time_x, W_t, Ll);

    // 4 Euler steps
    for (int it = 0; it < 4; it++) {
        gemm_kernel<1><<<dim3(Mtot/128, 2, 3), blk>>>(
            h, W_f1, hid, Mtot, Oo, Ll,
            (long)Mtot*Ll, (long)Ll*Oo, (long)Mtot*Oo, Oo, b_f1, nullptr, nullptr, 0);
        gemm_kernel<2><<<dim3(Mtot/128, 2, 3), blk>>>(
            hid, W_f2, h, Mtot, Ll, Oo,
            (long)Mtot*Oo, (long)Oo*Ll, (long)Mtot*Ll, Ll, b_f2, nullptr, nullptr, 0);
    }

    // qkv = mask * (h @ W_out + b_out + eco)    [3][M][H]
    gemm_kernel<3><<<dim3(Mtot/128, 2, 3), blk>>>(
        h, W_out, qkv, Mtot, Hh, Ll,
        (long)Mtot*Ll, (long)Ll*Hh, (long)Mtot*Hh, Hh, b_out, tran, eco, 0);

    // attention (512 threads, swizzled K tiles)
    size_t smem = (size_t)(32*1024 + 32*256 + 256*64) * sizeof(float); // 229376
    cudaFuncSetAttribute(attn_kernel, cudaFuncAttributeMaxDynamicSharedMemorySize, (int)smem);
    attn_kernel<<<dim3(Ss/32, Bb), 512, smem>>>(qkv, ctx);

    // out = ctx @ W_lin + b_lin   [M][P]
    gemm_kernel<4><<<dim3(Mtot/128, 1, 1), blk>>>(
        ctx, W_lin, out, Mtot, Pp, Hh,
        0L, 0L, 0L, 0, b_lin, nullptr, nullptr, 0);
}